// round 5
// baseline (speedup 1.0000x reference)
#include <cuda_runtime.h>
#include <cstdint>
#include <math.h>

#define T    2048
#define HD   1024
#define ID   2048
#define NE   8

// ---------------- scratch (__device__ globals; no allocation allowed) ----------------
__device__ float g_G [(size_t)NE * T * ID];   // expert gate outputs / h buffer (128 MB)
__device__ float g_U [(size_t)NE * T * ID];   // expert up outputs              (128 MB)
__device__ float g_SG[(size_t)T * ID];        // shared gate / h                ( 16 MB)
__device__ float g_SU[(size_t)T * ID];        // shared up                      ( 16 MB)
__device__ int   g_tok[NE * T];
__device__ float g_wt [NE * T];
__device__ int   g_cnt[NE];
__device__ float g_sump[NE];
__device__ float g_lse2[1];

// ---------------- small kernels ----------------
__global__ void k_reset() {
    int i = threadIdx.x;
    if (i < NE) { g_cnt[i] = 0; g_sump[i] = 0.f; }
    if (i == 0) g_lse2[0] = 0.f;
}

// one block (128 threads) per token: logits -> softmax -> top2 -> compaction + aux stats
__global__ void k_router(const float* __restrict__ x, const float* __restrict__ rw) {
    int t = blockIdx.x;
    int tid = threadIdx.x;
    float acc[NE];
#pragma unroll
    for (int e = 0; e < NE; e++) acc[e] = 0.f;
    const float* xr = x + (size_t)t * HD;
    for (int j = tid; j < HD; j += 128) {
        float xv = xr[j];
        const float* r = rw + (size_t)j * NE;
#pragma unroll
        for (int e = 0; e < NE; e++) acc[e] += xv * r[e];
    }
    __shared__ float sm[NE][128];
#pragma unroll
    for (int e = 0; e < NE; e++) sm[e][tid] = acc[e];
    __syncthreads();
    for (int s = 64; s > 0; s >>= 1) {
        if (tid < s) {
#pragma unroll
            for (int e = 0; e < NE; e++) sm[e][tid] += sm[e][tid + s];
        }
        __syncthreads();
    }
    if (tid == 0) {
        float l[NE];
#pragma unroll
        for (int e = 0; e < NE; e++) l[e] = sm[e][0];
        float m = l[0];
#pragma unroll
        for (int e = 1; e < NE; e++) m = fmaxf(m, l[e]);
        float p[NE]; float sum = 0.f;
#pragma unroll
        for (int e = 0; e < NE; e++) { p[e] = expf(l[e] - m); sum += p[e]; }
        float inv = 1.f / sum;
#pragma unroll
        for (int e = 0; e < NE; e++) p[e] *= inv;
        float lse = m + logf(sum);
        atomicAdd(&g_lse2[0], lse * lse);
#pragma unroll
        for (int e = 0; e < NE; e++) atomicAdd(&g_sump[e], p[e]);
        // top-2, lowest index wins ties (matches jax.lax.top_k)
        int i0 = 0;
#pragma unroll
        for (int e = 1; e < NE; e++) if (p[e] > p[i0]) i0 = e;
        int i1 = -1;
#pragma unroll
        for (int e = 0; e < NE; e++) {
            if (e == i0) continue;
            if (i1 < 0 || p[e] > p[i1]) i1 = e;
        }
        float w0 = p[i0], w1 = p[i1];
        float s2 = 1.f / (w0 + w1);
        w0 *= s2; w1 *= s2;
        int pos0 = atomicAdd(&g_cnt[i0], 1);
        g_tok[i0 * T + pos0] = t; g_wt[i0 * T + pos0] = w0;
        int pos1 = atomicAdd(&g_cnt[i1], 1);
        g_tok[i1 * T + pos1] = t; g_wt[i1 * T + pos1] = w1;
    }
}

__global__ void k_aux(float* __restrict__ out) {
    float fp = 0.f;
#pragma unroll
    for (int e = 0; e < NE; e++)
        fp += ((float)g_cnt[e] / (float)(T * 2)) * (g_sump[e] / (float)T);
    float lb = 0.01f * (float)NE * fp;
    float z  = 0.001f * (g_lse2[0] / (float)T);
    out[0] = lb + z;
}

// h = silu(g) * u ; rows beyond cnt[e] skipped (cnt==nullptr -> all rows)
__global__ void k_silu(const float* __restrict__ g, const float* __restrict__ u,
                       float* __restrict__ h, const int* __restrict__ cnt) {
    int row = blockIdx.y;
    if (cnt) {
        int e = row >> 11;
        int slot = row & (T - 1);
        if (slot >= cnt[e]) return;
    }
    int col = blockIdx.x * 256 + threadIdx.x;
    size_t idx = (size_t)row * ID + col;
    float gv = g[idx];
    h[idx] = gv / (1.f + expf(-gv)) * u[idx];
}

// ---------------- tf32 tensor-core GEMM ----------------
__device__ __forceinline__ uint32_t to_tf32(float f) {
    uint32_t r;
    asm("cvt.rna.tf32.f32 %0, %1;" : "=r"(r) : "f"(f));
    return r;
}

#define MMA_TF32(d, a, b)                                                      \
    asm volatile(                                                              \
        "mma.sync.aligned.m16n8k8.row.col.f32.tf32.tf32.f32 "                  \
        "{%0,%1,%2,%3},{%4,%5,%6,%7},{%8,%9},{%0,%1,%2,%3};"                   \
        : "+f"((d)[0]), "+f"((d)[1]), "+f"((d)[2]), "+f"((d)[3])               \
        : "r"((a)[0]), "r"((a)[1]), "r"((a)[2]), "r"((a)[3]),                  \
          "r"((b)[0]), "r"((b)[1]))

// C[m,n] = sum_k A[row(m), k] * B[k, n]
// GATHER: A row index gathered through toks; SCATTER: epilogue does
// atomicAdd(out[tok*ldc + n], w * acc) instead of store.
// Block tile 128x128, BK=16, 256 threads, warp tile 64x32.
template <bool GATHER, bool SCATTER>
__global__ __launch_bounds__(256)
void k_gemm(const float* __restrict__ A, int lda, size_t strideA,
            const float* __restrict__ B, int ldb, size_t strideB,
            float* __restrict__ C, int ldc, size_t strideC,
            const int* __restrict__ cnt, int Mfixed, int K,
            const int* __restrict__ tokall, const float* __restrict__ wtall) {
    int e = blockIdx.z;
    int M = cnt ? cnt[e] : Mfixed;
    int m0 = blockIdx.x * 128;
    if (m0 >= M) return;
    int n0 = blockIdx.y * 128;

    const float* Ap = A + (size_t)e * strideA;
    const float* Bp = B + (size_t)e * strideB;
    float* Cp = C + (size_t)e * strideC;
    const int*   toks = tokall ? tokall + e * T : nullptr;
    const float* wts  = wtall  ? wtall  + e * T : nullptr;

    int tid = threadIdx.x;
    int lane = tid & 31, wid = tid >> 5;
    int wm = wid & 1;        // 0..1 -> 64 rows each
    int wn = wid >> 1;       // 0..3 -> 32 cols each
    int grp = lane >> 2, tg = lane & 3;

    __shared__ uint32_t Asm[2][128 * 20];   // stride 20 floats (conflict-free frags)
    __shared__ uint32_t Bsm[2][16 * 136];   // stride 136 floats (conflict-free frags)

    // global A mapping: 2 threads per row, 8 floats each
    int aRow = tid >> 1;
    int aOff = (tid & 1) * 8;
    int slot = m0 + aRow;
    int sRow;
    {
        int s = (slot < M) ? slot : (M - 1);
        sRow = GATHER ? toks[s] : s;
    }
    const float* aPtr = Ap + (size_t)sRow * lda + aOff;
    // global B mapping: 16 threads per k-row, 8 floats each
    int bK = tid >> 4;
    int bN = (tid & 15) * 8;
    const float* bPtr = Bp + (size_t)bK * ldb + n0 + bN;

    float acc[4][4][4];
#pragma unroll
    for (int i = 0; i < 4; i++)
#pragma unroll
        for (int j = 0; j < 4; j++)
#pragma unroll
            for (int k = 0; k < 4; k++) acc[i][j][k] = 0.f;

    int ktiles = K / 16;
    float4 ra0, ra1, rb0, rb1;
    ra0 = *(const float4*)(aPtr);
    ra1 = *(const float4*)(aPtr + 4);
    rb0 = *(const float4*)(bPtr);
    rb1 = *(const float4*)(bPtr + 4);
    int buf = 0;

    {
        uint32_t* As = &Asm[buf][aRow * 20 + aOff];
        As[0] = to_tf32(ra0.x); As[1] = to_tf32(ra0.y); As[2] = to_tf32(ra0.z); As[3] = to_tf32(ra0.w);
        As[4] = to_tf32(ra1.x); As[5] = to_tf32(ra1.y); As[6] = to_tf32(ra1.z); As[7] = to_tf32(ra1.w);
        uint32_t* Bs = &Bsm[buf][bK * 136 + bN];
        Bs[0] = to_tf32(rb0.x); Bs[1] = to_tf32(rb0.y); Bs[2] = to_tf32(rb0.z); Bs[3] = to_tf32(rb0.w);
        Bs[4] = to_tf32(rb1.x); Bs[5] = to_tf32(rb1.y); Bs[6] = to_tf32(rb1.z); Bs[7] = to_tf32(rb1.w);
    }
    __syncthreads();

    for (int kt = 0; kt < ktiles; kt++) {
        bool has = (kt + 1 < ktiles);
        if (has) {
            const float* ap = aPtr + (kt + 1) * 16;
            ra0 = *(const float4*)(ap);
            ra1 = *(const float4*)(ap + 4);
            const float* bp = bPtr + (size_t)(kt + 1) * 16 * ldb;
            rb0 = *(const float4*)(bp);
            rb1 = *(const float4*)(bp + 4);
        }
        // compute on current buffer
#pragma unroll
        for (int kk = 0; kk < 16; kk += 8) {
            uint32_t a[4][4], b[4][2];
#pragma unroll
            for (int mt = 0; mt < 4; mt++) {
                int r0 = (wm * 64 + mt * 16 + grp) * 20;
                a[mt][0] = Asm[buf][r0 + kk + tg];
                a[mt][1] = Asm[buf][r0 + 160 + kk + tg];          // +8 rows
                a[mt][2] = Asm[buf][r0 + kk + tg + 4];
                a[mt][3] = Asm[buf][r0 + 160 + kk + tg + 4];
            }
#pragma unroll
            for (int nt = 0; nt < 4; nt++) {
                int c = wn * 32 + nt * 8 + grp;
                b[nt][0] = Bsm[buf][(kk + tg) * 136 + c];
                b[nt][1] = Bsm[buf][(kk + 4 + tg) * 136 + c];
            }
#pragma unroll
            for (int mt = 0; mt < 4; mt++)
#pragma unroll
                for (int nt = 0; nt < 4; nt++)
                    MMA_TF32(acc[mt][nt], a[mt], b[nt]);
        }
        if (has) {
            buf ^= 1;
            uint32_t* As = &Asm[buf][aRow * 20 + aOff];
            As[0] = to_tf32(ra0.x); As[1] = to_tf32(ra0.y); As[2] = to_tf32(ra0.z); As[3] = to_tf32(ra0.w);
            As[4] = to_tf32(ra1.x); As[5] = to_tf32(ra1.y); As[6] = to_tf32(ra1.z); As[7] = to_tf32(ra1.w);
            uint32_t* Bs = &Bsm[buf][bK * 136 + bN];
            Bs[0] = to_tf32(rb0.x); Bs[1] = to_tf32(rb0.y); Bs[2] = to_tf32(rb0.z); Bs[3] = to_tf32(rb0.w);
            Bs[4] = to_tf32(rb1.x); Bs[5] = to_tf32(rb1.y); Bs[6] = to_tf32(rb1.z); Bs[7] = to_tf32(rb1.w);
            __syncthreads();
        }
    }

    // epilogue
#pragma unroll
    for (int mt = 0; mt < 4; mt++) {
        int rbase = m0 + wm * 64 + mt * 16 + grp;
#pragma unroll
        for (int half = 0; half < 2; half++) {
            int r = rbase + half * 8;
            if (r < M) {
                if (SCATTER) {
                    int tok = toks[r];
                    float w = wts[r];
                    float* dst = C + (size_t)tok * ldc;
#pragma unroll
                    for (int nt = 0; nt < 4; nt++) {
                        int c = n0 + wn * 32 + nt * 8 + tg * 2;
                        atomicAdd(dst + c,     w * acc[mt][nt][half * 2 + 0]);
                        atomicAdd(dst + c + 1, w * acc[mt][nt][half * 2 + 1]);
                    }
                } else {
                    float* dst = Cp + (size_t)r * ldc;
#pragma unroll
                    for (int nt = 0; nt < 4; nt++) {
                        int c = n0 + wn * 32 + nt * 8 + tg * 2;
                        dst[c]     = acc[mt][nt][half * 2 + 0];
                        dst[c + 1] = acc[mt][nt][half * 2 + 1];
                    }
                }
            }
        }
    }
}

// ---------------- launch ----------------
extern "C" void kernel_launch(void* const* d_in, const int* in_sizes, int n_in,
                              void* d_out, int out_size) {
    const float* x  = (const float*)d_in[0];
    const float* rw = (const float*)d_in[1];
    const float* eg = (const float*)d_in[2];
    const float* eu = (const float*)d_in[3];
    const float* ed = (const float*)d_in[4];
    const float* sg = (const float*)d_in[5];
    const float* su = (const float*)d_in[6];
    const float* sd = (const float*)d_in[7];
    float* out = (float*)d_out;

    float *pG, *pU, *pSG, *pSU, *pwt, *psump, *plse2;
    int *ptok, *pcnt;
    cudaGetSymbolAddress((void**)&pG,   g_G);
    cudaGetSymbolAddress((void**)&pU,   g_U);
    cudaGetSymbolAddress((void**)&pSG,  g_SG);
    cudaGetSymbolAddress((void**)&pSU,  g_SU);
    cudaGetSymbolAddress((void**)&ptok, g_tok);
    cudaGetSymbolAddress((void**)&pwt,  g_wt);
    cudaGetSymbolAddress((void**)&pcnt, g_cnt);
    cudaGetSymbolAddress((void**)&psump, g_sump);
    cudaGetSymbolAddress((void**)&plse2, g_lse2);
    (void)psump; (void)plse2; (void)in_sizes; (void)n_in;

    k_reset<<<1, 32>>>();
    k_router<<<T, 128>>>(x, rw);
    if (out_size > T * HD) k_aux<<<1, 1>>>(out + (size_t)T * HD);

    // ---- shared expert chain (initializes out with a full store) ----
    k_gemm<false, false><<<dim3(T / 128, ID / 128, 1), 256>>>(
        x, HD, 0, sg, ID, 0, pSG, ID, 0, nullptr, T, HD, nullptr, nullptr);
    k_gemm<false, false><<<dim3(T / 128, ID / 128, 1), 256>>>(
        x, HD, 0, su, ID, 0, pSU, ID, 0, nullptr, T, HD, nullptr, nullptr);
    k_silu<<<dim3(ID / 256, T), 256>>>(pSG, pSU, pSG, nullptr);
    k_gemm<false, false><<<dim3(T / 128, HD / 128, 1), 256>>>(
        pSG, ID, 0, sd, HD, 0, out, HD, 0, nullptr, T, ID, nullptr, nullptr);

    // ---- routed experts (sparse, gathered rows; early-exit on cnt[e]) ----
    k_gemm<true, false><<<dim3(T / 128, ID / 128, NE), 256>>>(
        x, HD, 0, eg, ID, (size_t)HD * ID, pG, ID, (size_t)T * ID,
        pcnt, T, HD, ptok, nullptr);
    k_gemm<true, false><<<dim3(T / 128, ID / 128, NE), 256>>>(
        x, HD, 0, eu, ID, (size_t)HD * ID, pU, ID, (size_t)T * ID,
        pcnt, T, HD, ptok, nullptr);
    k_silu<<<dim3(ID / 256, NE * T), 256>>>(pG, pU, pG, pcnt);
    k_gemm<false, true><<<dim3(T / 128, HD / 128, NE), 256>>>(
        pG, ID, (size_t)T * ID, ed, HD, (size_t)ID * HD, out, HD, 0,
        pcnt, T, ID, ptok, pwt);
}

// round 6
// speedup vs baseline: 1.1475x; 1.1475x over previous
#include <cuda_runtime.h>
#include <cstdint>
#include <math.h>

#define T    2048
#define HD   1024
#define ID   2048
#define NE   8

// ---------------- scratch (__device__ globals; no allocation allowed) ----------------
__device__ float g_H [(size_t)NE * T * ID];   // routed h = silu(g)*u  (134 MB)
__device__ float g_SH[(size_t)T * ID];        // shared h              ( 16 MB)
__device__ int   g_tok[NE * T];
__device__ float g_wt [NE * T];
__device__ int   g_cnt[NE];
__device__ float g_sump[NE];
__device__ float g_lse2[1];

// ---------------- small kernels ----------------
__global__ void k_reset() {
    int i = threadIdx.x;
    if (i < NE) { g_cnt[i] = 0; g_sump[i] = 0.f; }
    if (i == 0) g_lse2[0] = 0.f;
}

// one block (128 threads) per token: logits -> softmax -> top2 -> compaction + aux stats
__global__ void k_router(const float* __restrict__ x, const float* __restrict__ rw) {
    int t = blockIdx.x;
    int tid = threadIdx.x;
    float acc[NE];
#pragma unroll
    for (int e = 0; e < NE; e++) acc[e] = 0.f;
    const float* xr = x + (size_t)t * HD;
    for (int j = tid; j < HD; j += 128) {
        float xv = xr[j];
        const float* r = rw + (size_t)j * NE;
#pragma unroll
        for (int e = 0; e < NE; e++) acc[e] += xv * r[e];
    }
    __shared__ float sm[NE][128];
#pragma unroll
    for (int e = 0; e < NE; e++) sm[e][tid] = acc[e];
    __syncthreads();
    for (int s = 64; s > 0; s >>= 1) {
        if (tid < s) {
#pragma unroll
            for (int e = 0; e < NE; e++) sm[e][tid] += sm[e][tid + s];
        }
        __syncthreads();
    }
    if (tid == 0) {
        float l[NE];
#pragma unroll
        for (int e = 0; e < NE; e++) l[e] = sm[e][0];
        float m = l[0];
#pragma unroll
        for (int e = 1; e < NE; e++) m = fmaxf(m, l[e]);
        float p[NE]; float sum = 0.f;
#pragma unroll
        for (int e = 0; e < NE; e++) { p[e] = expf(l[e] - m); sum += p[e]; }
        float inv = 1.f / sum;
#pragma unroll
        for (int e = 0; e < NE; e++) p[e] *= inv;
        float lse = m + logf(sum);
        atomicAdd(&g_lse2[0], lse * lse);
#pragma unroll
        for (int e = 0; e < NE; e++) atomicAdd(&g_sump[e], p[e]);
        // top-2, lowest index wins ties (matches jax.lax.top_k)
        int i0 = 0;
#pragma unroll
        for (int e = 1; e < NE; e++) if (p[e] > p[i0]) i0 = e;
        int i1 = -1;
#pragma unroll
        for (int e = 0; e < NE; e++) {
            if (e == i0) continue;
            if (i1 < 0 || p[e] > p[i1]) i1 = e;
        }
        float w0 = p[i0], w1 = p[i1];
        float s2 = 1.f / (w0 + w1);
        w0 *= s2; w1 *= s2;
        int pos0 = atomicAdd(&g_cnt[i0], 1);
        g_tok[i0 * T + pos0] = t; g_wt[i0 * T + pos0] = w0;
        int pos1 = atomicAdd(&g_cnt[i1], 1);
        g_tok[i1 * T + pos1] = t; g_wt[i1 * T + pos1] = w1;
    }
}

__global__ void k_aux(float* __restrict__ out) {
    float fp = 0.f;
#pragma unroll
    for (int e = 0; e < NE; e++)
        fp += ((float)g_cnt[e] / (float)(T * 2)) * (g_sump[e] / (float)T);
    float lb = 0.01f * (float)NE * fp;
    float z  = 0.001f * (g_lse2[0] / (float)T);
    out[0] = lb + z;
}

// ---------------- tf32 tensor-core GEMM ----------------
__device__ __forceinline__ uint32_t to_tf32(float f) {
    uint32_t r;
    asm("cvt.rna.tf32.f32 %0, %1;" : "=r"(r) : "f"(f));
    return r;
}

#define MMA_TF32(d, a, b)                                                      \
    asm volatile(                                                              \
        "mma.sync.aligned.m16n8k8.row.col.f32.tf32.tf32.f32 "                  \
        "{%0,%1,%2,%3},{%4,%5,%6,%7},{%8,%9},{%0,%1,%2,%3};"                   \
        : "+f"((d)[0]), "+f"((d)[1]), "+f"((d)[2]), "+f"((d)[3])               \
        : "r"((a)[0]), "r"((a)[1]), "r"((a)[2]), "r"((a)[3]),                  \
          "r"((b)[0]), "r"((b)[1]))

#define ASM_BUF 2560    // 128 rows * stride 20 (conflict-free frag loads)
#define BSM_BUF 2176    // 16 k-rows * stride 136 (conflict-free frag loads)

// C[m,n] = sum_k A[row(m), k] * B[k, n]
// GATHER:  A row gathered through toks
// SCATTER: epilogue atomicAdd(out[tok*ldc + n], w * acc)
// FUSED:   second B matrix (B2=up); epilogue stores silu(accB)*accB2
// Block tile 128x128, BK=16, 256 threads, warp tile 64x32, double-buffered smem.
template <bool GATHER, bool SCATTER, bool FUSED>
__global__ __launch_bounds__(256)
void k_gemm(const float* __restrict__ A, int lda, size_t strideA,
            const float* __restrict__ B, const float* __restrict__ B2,
            int ldb, size_t strideB,
            float* __restrict__ C, int ldc, size_t strideC,
            const int* __restrict__ cnt, int Mfixed, int K,
            const int* __restrict__ tokall, const float* __restrict__ wtall) {
    extern __shared__ uint32_t smem[];
    uint32_t* Asm  = smem;                               // 2 * ASM_BUF
    uint32_t* Bsm  = smem + 2 * ASM_BUF;                 // 2 * BSM_BUF
    uint32_t* B2sm = smem + 2 * ASM_BUF + 2 * BSM_BUF;   // 2 * BSM_BUF (FUSED only)

    int e = blockIdx.z;
    int M = cnt ? cnt[e] : Mfixed;
    int m0 = blockIdx.x * 128;
    if (m0 >= M) return;
    int n0 = blockIdx.y * 128;

    const float* Ap  = A + (size_t)e * strideA;
    const float* Bp  = B + (size_t)e * strideB;
    const float* B2p = FUSED ? (B2 + (size_t)e * strideB) : nullptr;
    float* Cp = C + (size_t)e * strideC;
    const int*   toks = tokall ? tokall + e * T : nullptr;
    const float* wts  = wtall  ? wtall  + e * T : nullptr;

    int tid = threadIdx.x;
    int lane = tid & 31, wid = tid >> 5;
    int wm = wid & 1;        // 0..1 -> 64 rows each
    int wn = wid >> 1;       // 0..3 -> 32 cols each
    int grp = lane >> 2, tg = lane & 3;

    // global A mapping: 2 threads per row, 8 floats each
    int aRow = tid >> 1;
    int aOff = (tid & 1) * 8;
    int sRow;
    {
        int s = m0 + aRow;
        s = (s < M) ? s : (M - 1);
        sRow = GATHER ? toks[s] : s;
    }
    const float* aPtr = Ap + (size_t)sRow * lda + aOff;
    // global B mapping: 16 threads per k-row, 8 floats each
    int bK = tid >> 4;
    int bN = (tid & 15) * 8;
    const float* bPtr  = Bp + (size_t)bK * ldb + n0 + bN;
    const float* b2Ptr = FUSED ? (B2p + (size_t)bK * ldb + n0 + bN) : nullptr;

    float accg[4][4][4];
    float accu[4][4][4];   // only used when FUSED (DCE otherwise)
#pragma unroll
    for (int i = 0; i < 4; i++)
#pragma unroll
        for (int j = 0; j < 4; j++)
#pragma unroll
            for (int k = 0; k < 4; k++) { accg[i][j][k] = 0.f; if (FUSED) accu[i][j][k] = 0.f; }

    int ktiles = K / 16;
    float4 ra0, ra1, rb0, rb1, rc0, rc1;
    ra0 = *(const float4*)(aPtr);
    ra1 = *(const float4*)(aPtr + 4);
    rb0 = *(const float4*)(bPtr);
    rb1 = *(const float4*)(bPtr + 4);
    if (FUSED) {
        rc0 = *(const float4*)(b2Ptr);
        rc1 = *(const float4*)(b2Ptr + 4);
    }
    int buf = 0;

#define STORE_TILES()                                                                   \
    do {                                                                                \
        uint32_t* As = &Asm[buf * ASM_BUF + aRow * 20 + aOff];                          \
        As[0] = to_tf32(ra0.x); As[1] = to_tf32(ra0.y);                                 \
        As[2] = to_tf32(ra0.z); As[3] = to_tf32(ra0.w);                                 \
        As[4] = to_tf32(ra1.x); As[5] = to_tf32(ra1.y);                                 \
        As[6] = to_tf32(ra1.z); As[7] = to_tf32(ra1.w);                                 \
        uint32_t* Bs = &Bsm[buf * BSM_BUF + bK * 136 + bN];                             \
        Bs[0] = to_tf32(rb0.x); Bs[1] = to_tf32(rb0.y);                                 \
        Bs[2] = to_tf32(rb0.z); Bs[3] = to_tf32(rb0.w);                                 \
        Bs[4] = to_tf32(rb1.x); Bs[5] = to_tf32(rb1.y);                                 \
        Bs[6] = to_tf32(rb1.z); Bs[7] = to_tf32(rb1.w);                                 \
        if (FUSED) {                                                                    \
            uint32_t* Cs = &B2sm[buf * BSM_BUF + bK * 136 + bN];                        \
            Cs[0] = to_tf32(rc0.x); Cs[1] = to_tf32(rc0.y);                             \
            Cs[2] = to_tf32(rc0.z); Cs[3] = to_tf32(rc0.w);                             \
            Cs[4] = to_tf32(rc1.x); Cs[5] = to_tf32(rc1.y);                             \
            Cs[6] = to_tf32(rc1.z); Cs[7] = to_tf32(rc1.w);                             \
        }                                                                               \
    } while (0)

    STORE_TILES();
    __syncthreads();

    for (int kt = 0; kt < ktiles; kt++) {
        bool has = (kt + 1 < ktiles);
        if (has) {
            const float* ap = aPtr + (kt + 1) * 16;
            ra0 = *(const float4*)(ap);
            ra1 = *(const float4*)(ap + 4);
            const float* bp = bPtr + (size_t)(kt + 1) * 16 * ldb;
            rb0 = *(const float4*)(bp);
            rb1 = *(const float4*)(bp + 4);
            if (FUSED) {
                const float* cp2 = b2Ptr + (size_t)(kt + 1) * 16 * ldb;
                rc0 = *(const float4*)(cp2);
                rc1 = *(const float4*)(cp2 + 4);
            }
        }
        // compute on current buffer
#pragma unroll
        for (int kk = 0; kk < 16; kk += 8) {
            uint32_t a[4][4], bg[4][2], bu[4][2];
#pragma unroll
            for (int mt = 0; mt < 4; mt++) {
                int r0 = buf * ASM_BUF + (wm * 64 + mt * 16 + grp) * 20;
                a[mt][0] = Asm[r0 + kk + tg];
                a[mt][1] = Asm[r0 + 160 + kk + tg];          // +8 rows
                a[mt][2] = Asm[r0 + kk + tg + 4];
                a[mt][3] = Asm[r0 + 160 + kk + tg + 4];
            }
#pragma unroll
            for (int nt = 0; nt < 4; nt++) {
                int c = wn * 32 + nt * 8 + grp;
                bg[nt][0] = Bsm[buf * BSM_BUF + (kk + tg) * 136 + c];
                bg[nt][1] = Bsm[buf * BSM_BUF + (kk + 4 + tg) * 136 + c];
                if (FUSED) {
                    bu[nt][0] = B2sm[buf * BSM_BUF + (kk + tg) * 136 + c];
                    bu[nt][1] = B2sm[buf * BSM_BUF + (kk + 4 + tg) * 136 + c];
                }
            }
#pragma unroll
            for (int mt = 0; mt < 4; mt++)
#pragma unroll
                for (int nt = 0; nt < 4; nt++) {
                    MMA_TF32(accg[mt][nt], a[mt], bg[nt]);
                    if (FUSED) MMA_TF32(accu[mt][nt], a[mt], bu[nt]);
                }
        }
        if (has) {
            buf ^= 1;
            STORE_TILES();
            __syncthreads();
        }
    }

    // epilogue
#pragma unroll
    for (int mt = 0; mt < 4; mt++) {
        int rbase = m0 + wm * 64 + mt * 16 + grp;
#pragma unroll
        for (int half = 0; half < 2; half++) {
            int r = rbase + half * 8;
            if (r < M) {
                if (SCATTER) {
                    int tok = toks[r];
                    float w = wts[r];
                    float* dst = C + (size_t)tok * ldc;
#pragma unroll
                    for (int nt = 0; nt < 4; nt++) {
                        int c = n0 + wn * 32 + nt * 8 + tg * 2;
                        atomicAdd(dst + c,     w * accg[mt][nt][half * 2 + 0]);
                        atomicAdd(dst + c + 1, w * accg[mt][nt][half * 2 + 1]);
                    }
                } else if (FUSED) {
                    float* dst = Cp + (size_t)r * ldc;
#pragma unroll
                    for (int nt = 0; nt < 4; nt++) {
                        int c = n0 + wn * 32 + nt * 8 + tg * 2;
#pragma unroll
                        for (int j = 0; j < 2; j++) {
                            float gv = accg[mt][nt][half * 2 + j];
                            float uv = accu[mt][nt][half * 2 + j];
                            dst[c + j] = gv * uv / (1.f + __expf(-gv));
                        }
                    }
                } else {
                    float* dst = Cp + (size_t)r * ldc;
#pragma unroll
                    for (int nt = 0; nt < 4; nt++) {
                        int c = n0 + wn * 32 + nt * 8 + tg * 2;
                        dst[c]     = accg[mt][nt][half * 2 + 0];
                        dst[c + 1] = accg[mt][nt][half * 2 + 1];
                    }
                }
            }
        }
    }
#undef STORE_TILES
}

// ---------------- launch ----------------
extern "C" void kernel_launch(void* const* d_in, const int* in_sizes, int n_in,
                              void* d_out, int out_size) {
    const float* x  = (const float*)d_in[0];
    const float* rw = (const float*)d_in[1];
    const float* eg = (const float*)d_in[2];
    const float* eu = (const float*)d_in[3];
    const float* ed = (const float*)d_in[4];
    const float* sg = (const float*)d_in[5];
    const float* su = (const float*)d_in[6];
    const float* sd = (const float*)d_in[7];
    float* out = (float*)d_out;

    float *pH, *pSH, *pwt;
    int *ptok, *pcnt;
    cudaGetSymbolAddress((void**)&pH,   g_H);
    cudaGetSymbolAddress((void**)&pSH,  g_SH);
    cudaGetSymbolAddress((void**)&ptok, g_tok);
    cudaGetSymbolAddress((void**)&pwt,  g_wt);
    cudaGetSymbolAddress((void**)&pcnt, g_cnt);
    (void)in_sizes; (void)n_in;

    const int SMEM_BASE  = (2 * ASM_BUF + 2 * BSM_BUF) * 4;  // 37888 B
    const int SMEM_FUSED = (2 * ASM_BUF + 4 * BSM_BUF) * 4;  // 55296 B
    cudaFuncSetAttribute(k_gemm<false, false, true>,
                         cudaFuncAttributeMaxDynamicSharedMemorySize, SMEM_FUSED);
    cudaFuncSetAttribute(k_gemm<true, false, true>,
                         cudaFuncAttributeMaxDynamicSharedMemorySize, SMEM_FUSED);

    k_reset<<<1, 32>>>();
    k_router<<<T, 128>>>(x, rw);
    if (out_size > T * HD) k_aux<<<1, 1>>>(out + (size_t)T * HD);

    // ---- shared expert: fused gate+up (writes h) then down (initializes out) ----
    k_gemm<false, false, true><<<dim3(T / 128, ID / 128, 1), 256, SMEM_FUSED>>>(
        x, HD, 0, sg, su, ID, 0, pSH, ID, 0, nullptr, T, HD, nullptr, nullptr);
    k_gemm<false, false, false><<<dim3(T / 128, HD / 128, 1), 256, SMEM_BASE>>>(
        pSH, ID, 0, sd, nullptr, HD, 0, out, HD, 0, nullptr, T, ID, nullptr, nullptr);

    // ---- routed experts: fused gather gate+up (writes h), then scatter down ----
    k_gemm<true, false, true><<<dim3(T / 128, ID / 128, NE), 256, SMEM_FUSED>>>(
        x, HD, 0, eg, eu, ID, (size_t)HD * ID, pH, ID, (size_t)T * ID,
        pcnt, T, HD, ptok, nullptr);
    k_gemm<false, true, false><<<dim3(T / 128, HD / 128, NE), 256, SMEM_BASE>>>(
        pH, ID, (size_t)T * ID, ed, nullptr, HD, (size_t)ID * HD, out, HD, 0,
        pcnt, T, ID, ptok, pwt);
}

// round 7
// speedup vs baseline: 1.1818x; 1.0299x over previous
#include <cuda_runtime.h>
#include <cstdint>
#include <math.h>

#define T    2048
#define HD   1024
#define ID   2048
#define NE   8

// ---------------- scratch (__device__ globals; no allocation allowed) ----------------
__device__ float g_H [(size_t)NE * T * ID];   // routed h = silu(g)*u  (134 MB)
__device__ float g_SH[(size_t)T * ID];        // shared h              ( 16 MB)
__device__ int   g_tok[NE * T];
__device__ float g_wt [NE * T];
__device__ int   g_cnt[NE];
__device__ float g_sump[NE];
__device__ float g_lse2[1];

// ---------------- small kernels ----------------
__global__ void k_reset() {
    int i = threadIdx.x;
    if (i < NE) { g_cnt[i] = 0; g_sump[i] = 0.f; }
    if (i == 0) g_lse2[0] = 0.f;
}

// one block (128 threads) per token: logits -> softmax -> top2 -> compaction + aux stats
__global__ void k_router(const float* __restrict__ x, const float* __restrict__ rw) {
    int t = blockIdx.x;
    int tid = threadIdx.x;
    float acc[NE];
#pragma unroll
    for (int e = 0; e < NE; e++) acc[e] = 0.f;
    const float* xr = x + (size_t)t * HD;
    for (int j = tid; j < HD; j += 128) {
        float xv = xr[j];
        const float* r = rw + (size_t)j * NE;
#pragma unroll
        for (int e = 0; e < NE; e++) acc[e] += xv * r[e];
    }
    __shared__ float sm[NE][128];
#pragma unroll
    for (int e = 0; e < NE; e++) sm[e][tid] = acc[e];
    __syncthreads();
    for (int s = 64; s > 0; s >>= 1) {
        if (tid < s) {
#pragma unroll
            for (int e = 0; e < NE; e++) sm[e][tid] += sm[e][tid + s];
        }
        __syncthreads();
    }
    if (tid == 0) {
        float l[NE];
#pragma unroll
        for (int e = 0; e < NE; e++) l[e] = sm[e][0];
        float m = l[0];
#pragma unroll
        for (int e = 1; e < NE; e++) m = fmaxf(m, l[e]);
        float p[NE]; float sum = 0.f;
#pragma unroll
        for (int e = 0; e < NE; e++) { p[e] = expf(l[e] - m); sum += p[e]; }
        float inv = 1.f / sum;
#pragma unroll
        for (int e = 0; e < NE; e++) p[e] *= inv;
        float lse = m + logf(sum);
        atomicAdd(&g_lse2[0], lse * lse);
#pragma unroll
        for (int e = 0; e < NE; e++) atomicAdd(&g_sump[e], p[e]);
        // top-2, lowest index wins ties (matches jax.lax.top_k)
        int i0 = 0;
#pragma unroll
        for (int e = 1; e < NE; e++) if (p[e] > p[i0]) i0 = e;
        int i1 = -1;
#pragma unroll
        for (int e = 0; e < NE; e++) {
            if (e == i0) continue;
            if (i1 < 0 || p[e] > p[i1]) i1 = e;
        }
        float w0 = p[i0], w1 = p[i1];
        float s2 = 1.f / (w0 + w1);
        w0 *= s2; w1 *= s2;
        int pos0 = atomicAdd(&g_cnt[i0], 1);
        g_tok[i0 * T + pos0] = t; g_wt[i0 * T + pos0] = w0;
        int pos1 = atomicAdd(&g_cnt[i1], 1);
        g_tok[i1 * T + pos1] = t; g_wt[i1 * T + pos1] = w1;
    }
}

__global__ void k_aux(float* __restrict__ out) {
    float fp = 0.f;
#pragma unroll
    for (int e = 0; e < NE; e++)
        fp += ((float)g_cnt[e] / (float)(T * 2)) * (g_sump[e] / (float)T);
    float lb = 0.01f * (float)NE * fp;
    float z  = 0.001f * (g_lse2[0] / (float)T);
    out[0] = lb + z;
}

// ---------------- tf32 tensor-core GEMM ----------------
__device__ __forceinline__ uint32_t to_tf32(float f) {
    uint32_t r;
    asm("cvt.rna.tf32.f32 %0, %1;" : "=r"(r) : "f"(f));
    return r;
}

#define MMA_TF32(d, a, b)                                                      \
    asm volatile(                                                              \
        "mma.sync.aligned.m16n8k8.row.col.f32.tf32.tf32.f32 "                  \
        "{%0,%1,%2,%3},{%4,%5,%6,%7},{%8,%9},{%0,%1,%2,%3};"                   \
        : "+f"((d)[0]), "+f"((d)[1]), "+f"((d)[2]), "+f"((d)[3])               \
        : "r"((a)[0]), "r"((a)[1]), "r"((a)[2]), "r"((a)[3]),                  \
          "r"((b)[0]), "r"((b)[1]))

#define ASM_BUF 2560    // 128 rows * stride 20 (conflict-free frag loads)
#define BSM_BUF 2176    // 16 k-rows * stride 136 (conflict-free frag loads)

// C[m,n] = sum_k A[row(m), k] * B[k, n]
// GATHER:  A row gathered through toks
// SCATTER: epilogue atomicAdd(out[tok*ldc + n], w * acc)
// FUSED:   second B matrix (B2=up); epilogue stores silu(accB)*accB2
// Block tile 128x128, BK=16, 512 threads, 16 warps in a 4x4 grid of 32x32
// warp tiles, double-buffered smem, register-staged global loads with tf32
// conversion at store time.
template <bool GATHER, bool SCATTER, bool FUSED>
__global__ __launch_bounds__(512, 1)
void k_gemm(const float* __restrict__ A, int lda, size_t strideA,
            const float* __restrict__ B, const float* __restrict__ B2,
            int ldb, size_t strideB,
            float* __restrict__ C, int ldc, size_t strideC,
            const int* __restrict__ cnt, int Mfixed, int K,
            const int* __restrict__ tokall, const float* __restrict__ wtall) {
    extern __shared__ uint32_t smem[];
    uint32_t* Asm  = smem;                               // 2 * ASM_BUF
    uint32_t* Bsm  = smem + 2 * ASM_BUF;                 // 2 * BSM_BUF
    uint32_t* B2sm = smem + 2 * ASM_BUF + 2 * BSM_BUF;   // 2 * BSM_BUF (FUSED only)

    int e = blockIdx.z;
    int M = cnt ? cnt[e] : Mfixed;
    int m0 = blockIdx.x * 128;
    if (m0 >= M) return;
    int n0 = blockIdx.y * 128;

    const float* Ap  = A + (size_t)e * strideA;
    const float* Bp  = B + (size_t)e * strideB;
    const float* B2p = FUSED ? (B2 + (size_t)e * strideB) : nullptr;
    float* Cp = C + (size_t)e * strideC;
    const int*   toks = tokall ? tokall + e * T : nullptr;
    const float* wts  = wtall  ? wtall  + e * T : nullptr;

    int tid = threadIdx.x;
    int lane = tid & 31, wid = tid >> 5;
    int wm = wid & 3;        // 0..3 -> 32 rows each
    int wn = wid >> 2;       // 0..3 -> 32 cols each
    int grp = lane >> 2, tg = lane & 3;

    // global A mapping: 4 threads per row, 4 floats each
    int aRow = tid >> 2;
    int aOff = (tid & 3) * 4;
    int sRow;
    {
        int s = m0 + aRow;
        s = (s < M) ? s : (M - 1);
        sRow = GATHER ? toks[s] : s;
    }
    const float* aPtr = Ap + (size_t)sRow * lda + aOff;
    // global B mapping: 32 threads per k-row, 4 floats each
    int bK = wid;
    int bN = (tid & 31) * 4;
    const float* bPtr  = Bp + (size_t)bK * ldb + n0 + bN;
    const float* b2Ptr = FUSED ? (B2p + (size_t)bK * ldb + n0 + bN) : nullptr;

    float accg[2][4][4];
    float accu[2][4][4];   // only used when FUSED (DCE otherwise)
#pragma unroll
    for (int i = 0; i < 2; i++)
#pragma unroll
        for (int j = 0; j < 4; j++)
#pragma unroll
            for (int k = 0; k < 4; k++) { accg[i][j][k] = 0.f; if (FUSED) accu[i][j][k] = 0.f; }

    int ktiles = K / 16;
    float4 ra, rb, rc;
    ra = *(const float4*)(aPtr);
    rb = *(const float4*)(bPtr);
    if (FUSED) rc = *(const float4*)(b2Ptr);
    int buf = 0;

#define STORE_TILES()                                                                   \
    do {                                                                                \
        uint32_t* As = &Asm[buf * ASM_BUF + aRow * 20 + aOff];                          \
        As[0] = to_tf32(ra.x); As[1] = to_tf32(ra.y);                                   \
        As[2] = to_tf32(ra.z); As[3] = to_tf32(ra.w);                                   \
        uint32_t* Bs = &Bsm[buf * BSM_BUF + bK * 136 + bN];                             \
        Bs[0] = to_tf32(rb.x); Bs[1] = to_tf32(rb.y);                                   \
        Bs[2] = to_tf32(rb.z); Bs[3] = to_tf32(rb.w);                                   \
        if (FUSED) {                                                                    \
            uint32_t* Cs = &B2sm[buf * BSM_BUF + bK * 136 + bN];                        \
            Cs[0] = to_tf32(rc.x); Cs[1] = to_tf32(rc.y);                               \
            Cs[2] = to_tf32(rc.z); Cs[3] = to_tf32(rc.w);                               \
        }                                                                               \
    } while (0)

    STORE_TILES();
    __syncthreads();

    for (int kt = 0; kt < ktiles; kt++) {
        bool has = (kt + 1 < ktiles);
        if (has) {
            ra = *(const float4*)(aPtr + (kt + 1) * 16);
            rb = *(const float4*)(bPtr + (size_t)(kt + 1) * 16 * ldb);
            if (FUSED) rc = *(const float4*)(b2Ptr + (size_t)(kt + 1) * 16 * ldb);
        }
        // compute on current buffer
#pragma unroll
        for (int kk = 0; kk < 16; kk += 8) {
            uint32_t a[2][4], bg[4][2], bu[4][2];
#pragma unroll
            for (int mt = 0; mt < 2; mt++) {
                int r0 = buf * ASM_BUF + (wm * 32 + mt * 16 + grp) * 20;
                a[mt][0] = Asm[r0 + kk + tg];
                a[mt][1] = Asm[r0 + 160 + kk + tg];          // +8 rows
                a[mt][2] = Asm[r0 + kk + tg + 4];
                a[mt][3] = Asm[r0 + 160 + kk + tg + 4];
            }
#pragma unroll
            for (int nt = 0; nt < 4; nt++) {
                int c = wn * 32 + nt * 8 + grp;
                bg[nt][0] = Bsm[buf * BSM_BUF + (kk + tg) * 136 + c];
                bg[nt][1] = Bsm[buf * BSM_BUF + (kk + 4 + tg) * 136 + c];
                if (FUSED) {
                    bu[nt][0] = B2sm[buf * BSM_BUF + (kk + tg) * 136 + c];
                    bu[nt][1] = B2sm[buf * BSM_BUF + (kk + 4 + tg) * 136 + c];
                }
            }
#pragma unroll
            for (int mt = 0; mt < 2; mt++)
#pragma unroll
                for (int nt = 0; nt < 4; nt++) {
                    MMA_TF32(accg[mt][nt], a[mt], bg[nt]);
                    if (FUSED) MMA_TF32(accu[mt][nt], a[mt], bu[nt]);
                }
        }
        if (has) {
            buf ^= 1;
            STORE_TILES();
            __syncthreads();
        }
    }

    // epilogue
#pragma unroll
    for (int mt = 0; mt < 2; mt++) {
        int rbase = m0 + wm * 32 + mt * 16 + grp;
#pragma unroll
        for (int half = 0; half < 2; half++) {
            int r = rbase + half * 8;
            if (r < M) {
                if (SCATTER) {
                    int tok = toks[r];
                    float w = wts[r];
                    float* dst = C + (size_t)tok * ldc;
#pragma unroll
                    for (int nt = 0; nt < 4; nt++) {
                        int c = n0 + wn * 32 + nt * 8 + tg * 2;
                        atomicAdd(dst + c,     w * accg[mt][nt][half * 2 + 0]);
                        atomicAdd(dst + c + 1, w * accg[mt][nt][half * 2 + 1]);
                    }
                } else if (FUSED) {
                    float* dst = Cp + (size_t)r * ldc;
#pragma unroll
                    for (int nt = 0; nt < 4; nt++) {
                        int c = n0 + wn * 32 + nt * 8 + tg * 2;
#pragma unroll
                        for (int j = 0; j < 2; j++) {
                            float gv = accg[mt][nt][half * 2 + j];
                            float uv = accu[mt][nt][half * 2 + j];
                            dst[c + j] = gv * uv / (1.f + __expf(-gv));
                        }
                    }
                } else {
                    float* dst = Cp + (size_t)r * ldc;
#pragma unroll
                    for (int nt = 0; nt < 4; nt++) {
                        int c = n0 + wn * 32 + nt * 8 + tg * 2;
                        dst[c]     = accg[mt][nt][half * 2 + 0];
                        dst[c + 1] = accg[mt][nt][half * 2 + 1];
                    }
                }
            }
        }
    }
#undef STORE_TILES
}

// ---------------- launch ----------------
extern "C" void kernel_launch(void* const* d_in, const int* in_sizes, int n_in,
                              void* d_out, int out_size) {
    const float* x  = (const float*)d_in[0];
    const float* rw = (const float*)d_in[1];
    const float* eg = (const float*)d_in[2];
    const float* eu = (const float*)d_in[3];
    const float* ed = (const float*)d_in[4];
    const float* sg = (const float*)d_in[5];
    const float* su = (const float*)d_in[6];
    const float* sd = (const float*)d_in[7];
    float* out = (float*)d_out;

    float *pH, *pSH, *pwt;
    int *ptok, *pcnt;
    cudaGetSymbolAddress((void**)&pH,   g_H);
    cudaGetSymbolAddress((void**)&pSH,  g_SH);
    cudaGetSymbolAddress((void**)&ptok, g_tok);
    cudaGetSymbolAddress((void**)&pwt,  g_wt);
    cudaGetSymbolAddress((void**)&pcnt, g_cnt);
    (void)in_sizes; (void)n_in;

    const int SMEM_BASE  = (2 * ASM_BUF + 2 * BSM_BUF) * 4;  // 37888 B
    const int SMEM_FUSED = (2 * ASM_BUF + 4 * BSM_BUF) * 4;  // 55296 B
    cudaFuncSetAttribute(k_gemm<false, false, true>,
                         cudaFuncAttributeMaxDynamicSharedMemorySize, SMEM_FUSED);
    cudaFuncSetAttribute(k_gemm<true, false, true>,
                         cudaFuncAttributeMaxDynamicSharedMemorySize, SMEM_FUSED);

    k_reset<<<1, 32>>>();
    k_router<<<T, 128>>>(x, rw);
    if (out_size > T * HD) k_aux<<<1, 1>>>(out + (size_t)T * HD);

    // ---- shared expert: fused gate+up (writes h) then down (initializes out) ----
    k_gemm<false, false, true><<<dim3(T / 128, ID / 128, 1), 512, SMEM_FUSED>>>(
        x, HD, 0, sg, su, ID, 0, pSH, ID, 0, nullptr, T, HD, nullptr, nullptr);
    k_gemm<false, false, false><<<dim3(T / 128, HD / 128, 1), 512, SMEM_BASE>>>(
        pSH, ID, 0, sd, nullptr, HD, 0, out, HD, 0, nullptr, T, ID, nullptr, nullptr);

    // ---- routed experts: fused gather gate+up (writes h), then scatter down ----
    k_gemm<true, false, true><<<dim3(T / 128, ID / 128, NE), 512, SMEM_FUSED>>>(
        x, HD, 0, eg, eu, ID, (size_t)HD * ID, pH, ID, (size_t)T * ID,
        pcnt, T, HD, ptok, nullptr);
    k_gemm<false, true, false><<<dim3(T / 128, HD / 128, NE), 512, SMEM_BASE>>>(
        pH, ID, (size_t)T * ID, ed, nullptr, HD, (size_t)ID * HD, out, HD, 0,
        pcnt, T, ID, ptok, pwt);
}

// round 10
// speedup vs baseline: 1.1863x; 1.0038x over previous
#include <cuda_runtime.h>
#include <cstdint>
#include <math.h>

#define T    2048
#define HD   1024
#define ID   2048
#define NE   8

// ---------------- scratch (__device__ globals; no allocation allowed) ----------------
__device__ float g_H [(size_t)NE * T * ID];   // routed h = silu(g)*u  (134 MB)
__device__ float g_SH[(size_t)T * ID];        // shared h              ( 16 MB)
__device__ int   g_tok[NE * T];
__device__ float g_wt [NE * T];
__device__ int   g_cnt[NE];
__device__ float g_sump[NE];
__device__ float g_lse2[1];

// ---------------- small kernels ----------------
__global__ void k_reset() {
    int i = threadIdx.x;
    if (i < NE) { g_cnt[i] = 0; g_sump[i] = 0.f; }
    if (i == 0) g_lse2[0] = 0.f;
}

// one block (128 threads) per token: logits -> softmax -> top2 -> compaction + aux stats
__global__ void k_router(const float* __restrict__ x, const float* __restrict__ rw) {
    int t = blockIdx.x;
    int tid = threadIdx.x;
    float acc[NE];
#pragma unroll
    for (int e = 0; e < NE; e++) acc[e] = 0.f;
    const float* xr = x + (size_t)t * HD;
    for (int j = tid; j < HD; j += 128) {
        float xv = xr[j];
        const float* r = rw + (size_t)j * NE;
#pragma unroll
        for (int e = 0; e < NE; e++) acc[e] += xv * r[e];
    }
    __shared__ float sm[NE][128];
#pragma unroll
    for (int e = 0; e < NE; e++) sm[e][tid] = acc[e];
    __syncthreads();
    for (int s = 64; s > 0; s >>= 1) {
        if (tid < s) {
#pragma unroll
            for (int e = 0; e < NE; e++) sm[e][tid] += sm[e][tid + s];
        }
        __syncthreads();
    }
    if (tid == 0) {
        float l[NE];
#pragma unroll
        for (int e = 0; e < NE; e++) l[e] = sm[e][0];
        float m = l[0];
#pragma unroll
        for (int e = 1; e < NE; e++) m = fmaxf(m, l[e]);
        float p[NE]; float sum = 0.f;
#pragma unroll
        for (int e = 0; e < NE; e++) { p[e] = expf(l[e] - m); sum += p[e]; }
        float inv = 1.f / sum;
#pragma unroll
        for (int e = 0; e < NE; e++) p[e] *= inv;
        float lse = m + logf(sum);
        atomicAdd(&g_lse2[0], lse * lse);
#pragma unroll
        for (int e = 0; e < NE; e++) atomicAdd(&g_sump[e], p[e]);
        // top-2, lowest index wins ties (matches jax.lax.top_k)
        int i0 = 0;
#pragma unroll
        for (int e = 1; e < NE; e++) if (p[e] > p[i0]) i0 = e;
        int i1 = -1;
#pragma unroll
        for (int e = 0; e < NE; e++) {
            if (e == i0) continue;
            if (i1 < 0 || p[e] > p[i1]) i1 = e;
        }
        float w0 = p[i0], w1 = p[i1];
        float s2 = 1.f / (w0 + w1);
        w0 *= s2; w1 *= s2;
        int pos0 = atomicAdd(&g_cnt[i0], 1);
        g_tok[i0 * T + pos0] = t; g_wt[i0 * T + pos0] = w0;
        int pos1 = atomicAdd(&g_cnt[i1], 1);
        g_tok[i1 * T + pos1] = t; g_wt[i1 * T + pos1] = w1;
    }
}

__global__ void k_aux(float* __restrict__ out) {
    float fp = 0.f;
#pragma unroll
    for (int e = 0; e < NE; e++)
        fp += ((float)g_cnt[e] / (float)(T * 2)) * (g_sump[e] / (float)T);
    float lb = 0.01f * (float)NE * fp;
    float z  = 0.001f * (g_lse2[0] / (float)T);
    out[0] = lb + z;
}

// ---------------- tf32 tensor-core GEMM ----------------
__device__ __forceinline__ uint32_t to_tf32(float f) {
    uint32_t r;
    asm("cvt.rna.tf32.f32 %0, %1;" : "=r"(r) : "f"(f));
    return r;
}

#define MMA_TF32(d, a, b)                                                      \
    asm volatile(                                                              \
        "mma.sync.aligned.m16n8k8.row.col.f32.tf32.tf32.f32 "                  \
        "{%0,%1,%2,%3},{%4,%5,%6,%7},{%8,%9},{%0,%1,%2,%3};"                   \
        : "+f"((d)[0]), "+f"((d)[1]), "+f"((d)[2]), "+f"((d)[3])               \
        : "r"((a)[0]), "r"((a)[1]), "r"((a)[2]), "r"((a)[3]),                  \
          "r"((b)[0]), "r"((b)[1]))

#define ASM_BUF 2560    // 128 rows * stride 20 (conflict-free frag loads)
#define BSM_BUF 2176    // 16 k-rows * stride 136 (conflict-free frag loads)

// C[m,n] = sum_k A[row(m), k] * B[k, n]
// GATHER:  A row gathered through toks
// SCATTER: epilogue atomicAdd(out[tok*ldc + n], w * acc)
// FUSED:   second B matrix (B2=up); epilogue stores silu(accB)*accB2
// Block tile 128x128, BK=16, 512 threads, 16 warps in a 4x4 grid of 32x32
// warp tiles, double-buffered smem, register-staged global loads with tf32
// conversion at store time.
template <bool GATHER, bool SCATTER, bool FUSED>
__global__ __launch_bounds__(512, 1)
void k_gemm(const float* __restrict__ A, int lda, size_t strideA,
            const float* __restrict__ B, const float* __restrict__ B2,
            int ldb, size_t strideB,
            float* __restrict__ C, int ldc, size_t strideC,
            const int* __restrict__ cnt, int Mfixed, int K,
            const int* __restrict__ tokall, const float* __restrict__ wtall) {
    extern __shared__ uint32_t smem[];
    uint32_t* Asm  = smem;                               // 2 * ASM_BUF
    uint32_t* Bsm  = smem + 2 * ASM_BUF;                 // 2 * BSM_BUF
    uint32_t* B2sm = smem + 2 * ASM_BUF + 2 * BSM_BUF;   // 2 * BSM_BUF (FUSED only)

    int e = blockIdx.z;
    int M = cnt ? cnt[e] : Mfixed;
    int m0 = blockIdx.x * 128;
    if (m0 >= M) return;
    int n0 = blockIdx.y * 128;

    const float* Ap  = A + (size_t)e * strideA;
    const float* Bp  = B + (size_t)e * strideB;
    const float* B2p = FUSED ? (B2 + (size_t)e * strideB) : nullptr;
    float* Cp = C + (size_t)e * strideC;
    const int*   toks = tokall ? tokall + e * T : nullptr;
    const float* wts  = wtall  ? wtall  + e * T : nullptr;

    int tid = threadIdx.x;
    int lane = tid & 31, wid = tid >> 5;
    int wm = wid & 3;        // 0..3 -> 32 rows each
    int wn = wid >> 2;       // 0..3 -> 32 cols each
    int grp = lane >> 2, tg = lane & 3;

    // global A mapping: 4 threads per row, 4 floats each
    int aRow = tid >> 2;
    int aOff = (tid & 3) * 4;
    int sRow;
    {
        int s = m0 + aRow;
        s = (s < M) ? s : (M - 1);
        sRow = GATHER ? toks[s] : s;
    }
    const float* aPtr = Ap + (size_t)sRow * lda + aOff;
    // global B mapping: 32 threads per k-row, 4 floats each
    int bK = wid;
    int bN = (tid & 31) * 4;
    const float* bPtr  = Bp + (size_t)bK * ldb + n0 + bN;
    const float* b2Ptr = FUSED ? (B2p + (size_t)bK * ldb + n0 + bN) : nullptr;

    float accg[2][4][4];
    float accu[2][4][4];   // only used when FUSED (DCE otherwise)
#pragma unroll
    for (int i = 0; i < 2; i++)
#pragma unroll
        for (int j = 0; j < 4; j++)
#pragma unroll
            for (int k = 0; k < 4; k++) { accg[i][j][k] = 0.f; if (FUSED) accu[i][j][k] = 0.f; }

    int ktiles = K / 16;
    float4 ra, rb, rc;
    ra = *(const float4*)(aPtr);
    rb = *(const float4*)(bPtr);
    if (FUSED) rc = *(const float4*)(b2Ptr);
    int buf = 0;

#define STORE_TILES()                                                                   \
    do {                                                                                \
        uint32_t* As = &Asm[buf * ASM_BUF + aRow * 20 + aOff];                          \
        As[0] = to_tf32(ra.x); As[1] = to_tf32(ra.y);                                   \
        As[2] = to_tf32(ra.z); As[3] = to_tf32(ra.w);                                   \
        uint32_t* Bs = &Bsm[buf * BSM_BUF + bK * 136 + bN];                             \
        Bs[0] = to_tf32(rb.x); Bs[1] = to_tf32(rb.y);                                   \
        Bs[2] = to_tf32(rb.z); Bs[3] = to_tf32(rb.w);                                   \
        if (FUSED) {                                                                    \
            uint32_t* Cs = &B2sm[buf * BSM_BUF + bK * 136 + bN];                        \
            Cs[0] = to_tf32(rc.x); Cs[1] = to_tf32(rc.y);                               \
            Cs[2] = to_tf32(rc.z); Cs[3] = to_tf32(rc.w);                               \
        }                                                                               \
    } while (0)

    STORE_TILES();
    __syncthreads();

    for (int kt = 0; kt < ktiles; kt++) {
        bool has = (kt + 1 < ktiles);
        if (has) {
            ra = *(const float4*)(aPtr + (kt + 1) * 16);
            rb = *(const float4*)(bPtr + (size_t)(kt + 1) * 16 * ldb);
            if (FUSED) rc = *(const float4*)(b2Ptr + (size_t)(kt + 1) * 16 * ldb);
        }
        // compute on current buffer
#pragma unroll
        for (int kk = 0; kk < 16; kk += 8) {
            uint32_t a[2][4], bg[4][2], bu[4][2];
#pragma unroll
            for (int mt = 0; mt < 2; mt++) {
                int r0 = buf * ASM_BUF + (wm * 32 + mt * 16 + grp) * 20;
                a[mt][0] = Asm[r0 + kk + tg];
                a[mt][1] = Asm[r0 + 160 + kk + tg];          // +8 rows
                a[mt][2] = Asm[r0 + kk + tg + 4];
                a[mt][3] = Asm[r0 + 160 + kk + tg + 4];
            }
#pragma unroll
            for (int nt = 0; nt < 4; nt++) {
                int c = wn * 32 + nt * 8 + grp;
                bg[nt][0] = Bsm[buf * BSM_BUF + (kk + tg) * 136 + c];
                bg[nt][1] = Bsm[buf * BSM_BUF + (kk + 4 + tg) * 136 + c];
                if (FUSED) {
                    bu[nt][0] = B2sm[buf * BSM_BUF + (kk + tg) * 136 + c];
                    bu[nt][1] = B2sm[buf * BSM_BUF + (kk + 4 + tg) * 136 + c];
                }
            }
#pragma unroll
            for (int mt = 0; mt < 2; mt++)
#pragma unroll
                for (int nt = 0; nt < 4; nt++) {
                    MMA_TF32(accg[mt][nt], a[mt], bg[nt]);
                    if (FUSED) MMA_TF32(accu[mt][nt], a[mt], bu[nt]);
                }
        }
        if (has) {
            buf ^= 1;
            STORE_TILES();
            __syncthreads();
        }
    }

    // epilogue
#pragma unroll
    for (int mt = 0; mt < 2; mt++) {
        int rbase = m0 + wm * 32 + mt * 16 + grp;
#pragma unroll
        for (int half = 0; half < 2; half++) {
            int r = rbase + half * 8;
            if (r < M) {
                if (SCATTER) {
                    int tok = toks[r];
                    float w = wts[r];
                    float* dst = C + (size_t)tok * ldc;
#pragma unroll
                    for (int nt = 0; nt < 4; nt++) {
                        int c = n0 + wn * 32 + nt * 8 + tg * 2;
                        atomicAdd(dst + c,     w * accg[mt][nt][half * 2 + 0]);
                        atomicAdd(dst + c + 1, w * accg[mt][nt][half * 2 + 1]);
                    }
                } else if (FUSED) {
                    float* dst = Cp + (size_t)r * ldc;
#pragma unroll
                    for (int nt = 0; nt < 4; nt++) {
                        int c = n0 + wn * 32 + nt * 8 + tg * 2;
#pragma unroll
                        for (int j = 0; j < 2; j++) {
                            float gv = accg[mt][nt][half * 2 + j];
                            float uv = accu[mt][nt][half * 2 + j];
                            dst[c + j] = gv * uv / (1.f + __expf(-gv));
                        }
                    }
                } else {
                    float* dst = Cp + (size_t)r * ldc;
#pragma unroll
                    for (int nt = 0; nt < 4; nt++) {
                        int c = n0 + wn * 32 + nt * 8 + tg * 2;
                        dst[c]     = accg[mt][nt][half * 2 + 0];
                        dst[c + 1] = accg[mt][nt][half * 2 + 1];
                    }
                }
            }
        }
    }
#undef STORE_TILES
}

// ---------------- launch ----------------
extern "C" void kernel_launch(void* const* d_in, const int* in_sizes, int n_in,
                              void* d_out, int out_size) {
    const float* x  = (const float*)d_in[0];
    const float* rw = (const float*)d_in[1];
    const float* eg = (const float*)d_in[2];
    const float* eu = (const float*)d_in[3];
    const float* ed = (const float*)d_in[4];
    const float* sg = (const float*)d_in[5];
    const float* su = (const float*)d_in[6];
    const float* sd = (const float*)d_in[7];
    float* out = (float*)d_out;

    float *pH, *pSH, *pwt;
    int *ptok, *pcnt;
    cudaGetSymbolAddress((void**)&pH,   g_H);
    cudaGetSymbolAddress((void**)&pSH,  g_SH);
    cudaGetSymbolAddress((void**)&ptok, g_tok);
    cudaGetSymbolAddress((void**)&pwt,  g_wt);
    cudaGetSymbolAddress((void**)&pcnt, g_cnt);
    (void)in_sizes; (void)n_in;

    const int SMEM_BASE  = (2 * ASM_BUF + 2 * BSM_BUF) * 4;  // 37888 B
    const int SMEM_FUSED = (2 * ASM_BUF + 4 * BSM_BUF) * 4;  // 55296 B
    cudaFuncSetAttribute(k_gemm<false, false, true>,
                         cudaFuncAttributeMaxDynamicSharedMemorySize, SMEM_FUSED);
    cudaFuncSetAttribute(k_gemm<true, false, true>,
                         cudaFuncAttributeMaxDynamicSharedMemorySize, SMEM_FUSED);

    k_reset<<<1, 32>>>();
    k_router<<<T, 128>>>(x, rw);
    if (out_size > T * HD) k_aux<<<1, 1>>>(out + (size_t)T * HD);

    // ---- shared expert: fused gate+up (writes h) then down (initializes out) ----
    k_gemm<false, false, true><<<dim3(T / 128, ID / 128, 1), 512, SMEM_FUSED>>>(
        x, HD, 0, sg, su, ID, 0, pSH, ID, 0, nullptr, T, HD, nullptr, nullptr);
    k_gemm<false, false, false><<<dim3(T / 128, HD / 128, 1), 512, SMEM_BASE>>>(
        pSH, ID, 0, sd, nullptr, HD, 0, out, HD, 0, nullptr, T, ID, nullptr, nullptr);

    // ---- routed experts: fused gather gate+up (writes h), then scatter down ----
    k_gemm<true, false, true><<<dim3(T / 128, ID / 128, NE), 512, SMEM_FUSED>>>(
        x, HD, 0, eg, eu, ID, (size_t)HD * ID, pH, ID, (size_t)T * ID,
        pcnt, T, HD, ptok, nullptr);
    k_gemm<false, true, false><<<dim3(T / 128, HD / 128, NE), 512, SMEM_BASE>>>(
        pH, ID, (size_t)T * ID, ed, nullptr, HD, (size_t)ID * HD, out, HD, 0,
        pcnt, T, ID, ptok, pwt);
}